// round 3
// baseline (speedup 1.0000x reference)
#include <cuda_runtime.h>
#include <math.h>

#define LBL 32
#define MAXB 8
#define DELTA_AGG 0.5f
#define DELTA_DIS 1.5f
#define REG_W 0.001f

// device-global scratch (no allocations allowed)
__device__ unsigned long long g_pcnt[MAXB][LBL];  // lo32 = cnt (mask), hi32 = cnt_k (mask&kernel)
__device__ float4 g_sum[MAXB][LBL];               // emb sums over kernel region
__device__ float  g_agg[MAXB];                    // sum of val/cnt[label] over contributing pixels
__device__ float4 g_mean[MAXB][LBL];
__device__ float  g_w[MAXB][LBL];                 // nz ? 1/max(cnt,1) : 0

__device__ __forceinline__ float wsum(float v) {
#pragma unroll
    for (int o = 16; o; o >>= 1) v += __shfl_xor_sync(0xffffffffu, v, o);
    return v;
}

__device__ __forceinline__ void red_add_v4f32(float4* p, float a, float b, float c, float d) {
    asm volatile("red.global.add.v4.f32 [%0], {%1, %2, %3, %4};"
                 :: "l"(p), "f"(a), "f"(b), "f"(c), "f"(d) : "memory");
}

__global__ void pan_zero_kernel() {
    int i = threadIdx.x;
    unsigned long long* pc = &g_pcnt[0][0];
    float4* ps = &g_sum[0][0];
    for (int k = i; k < MAXB * LBL; k += blockDim.x) {
        pc[k] = 0ULL;
        ps[k] = make_float4(0.f, 0.f, 0.f, 0.f);
    }
    if (i < MAXB) g_agg[i] = 0.f;
}

// Pass 1: counts (packed u64 RED) + kernel-region emb sums (v4 f32 RED). No shared atomics.
__global__ void pan_accum_kernel(const float4* __restrict__ emb,
                                 const int4* __restrict__ inst,
                                 const float4* __restrict__ ker,
                                 const float4* __restrict__ tmk,
                                 int Nv) {  // Nv = Npix/4
    const int b = blockIdx.y;
    const int4*   ip = inst + (size_t)b * Nv;
    const float4* tm = tmk + (size_t)b * Nv;
    const float4* kn = ker + (size_t)b * Nv;
    const float4* ee = emb + (size_t)b * 4 * Nv;

    for (int i = blockIdx.x * blockDim.x + threadIdx.x; i < Nv;
         i += gridDim.x * blockDim.x) {
        const int4   v4 = ip[i];
        const float4 t4 = tm[i];
        const float4 k4 = kn[i];
        const float4 e0 = ee[i];
        const float4 e1 = ee[i + Nv];
        const float4 e2 = ee[i + 2 * Nv];
        const float4 e3 = ee[i + 3 * Nv];

        const int   vs[4] = {v4.x & 31, v4.y & 31, v4.z & 31, v4.w & 31};
        const float ts[4] = {t4.x, t4.y, t4.z, t4.w};
        const float ks[4] = {k4.x, k4.y, k4.z, k4.w};
        const float a0[4] = {e0.x, e0.y, e0.z, e0.w};
        const float a1[4] = {e1.x, e1.y, e1.z, e1.w};
        const float a2[4] = {e2.x, e2.y, e2.z, e2.w};
        const float a3[4] = {e3.x, e3.y, e3.z, e3.w};

#pragma unroll
        for (int j = 0; j < 4; ++j) {
            const bool t  = ts[j] > 0.5f;
            const int  v  = vs[j];
            const bool li = t && (v > 0);
            const bool kk = li && (ks[j] > 0.5f);
            if (li)
                atomicAdd(&g_pcnt[b][v], 1ULL + (kk ? (1ULL << 32) : 0ULL));
            if (kk)
                red_add_v4f32(&g_sum[b][v], a0[j], a1[j], a2[j], a3[j]);
        }
    }
}

// means + per-label agg weights
__global__ void pan_mean_kernel() {  // grid = B, block = 32
    const int b = blockIdx.x;
    const int l = threadIdx.x;
    const unsigned long long p = g_pcnt[b][l];
    const float cnt  = (float)(unsigned)(p & 0xffffffffu);
    const float cntk = (float)(unsigned)(p >> 32);
    const float4 s = g_sum[b][l];
    const float ic = (l > 0) ? 1.0f / fmaxf(cntk, 1.0f) : 0.0f;   // row 0 forced to 0
    g_mean[b][l] = make_float4(s.x * ic, s.y * ic, s.z * ic, s.w * ic);
    g_w[b][l] = (l > 0 && cntk > 0.0f) ? 1.0f / fmaxf(cnt, 1.0f) : 0.0f;
}

// Pass 2: per-pixel aggregation value with precomputed per-label weight -> scalar sum.
__global__ void pan_agg_kernel(const float4* __restrict__ emb,
                               const int4* __restrict__ inst,
                               const float4* __restrict__ tmk,
                               int Nv) {
    const int b = blockIdx.y;
    __shared__ float4 sm[LBL];
    __shared__ float  sw[LBL];
    __shared__ float  sred[8];
    if (threadIdx.x < LBL) {
        sm[threadIdx.x] = g_mean[b][threadIdx.x];
        sw[threadIdx.x] = g_w[b][threadIdx.x];
    }
    __syncthreads();

    const int4*   ip = inst + (size_t)b * Nv;
    const float4* tm = tmk + (size_t)b * Nv;
    const float4* ee = emb + (size_t)b * 4 * Nv;

    float acc = 0.0f;
    for (int i = blockIdx.x * blockDim.x + threadIdx.x; i < Nv;
         i += gridDim.x * blockDim.x) {
        const int4   v4 = ip[i];
        const float4 t4 = tm[i];
        const float4 e0 = ee[i];
        const float4 e1 = ee[i + Nv];
        const float4 e2 = ee[i + 2 * Nv];
        const float4 e3 = ee[i + 3 * Nv];

        const int   vs[4] = {v4.x & 31, v4.y & 31, v4.z & 31, v4.w & 31};
        const float ts[4] = {t4.x, t4.y, t4.z, t4.w};
        const float a0[4] = {e0.x, e0.y, e0.z, e0.w};
        const float a1[4] = {e1.x, e1.y, e1.z, e1.w};
        const float a2[4] = {e2.x, e2.y, e2.z, e2.w};
        const float a3[4] = {e3.x, e3.y, e3.z, e3.w};

#pragma unroll
        for (int j = 0; j < 4; ++j) {
            const bool t = ts[j] > 0.5f;
            const int  v = vs[j];
            if (t && v > 0) {
                const float4 m = sm[v];
                float dx = a0[j] - m.x;
                float dy = a1[j] - m.y;
                float dz = a2[j] - m.z;
                float dw = a3[j] - m.w;
                float sq = dx * dx + dy * dy + dz * dz + dw * dw;
                float r  = fmaxf(sqrtf(sq) - DELTA_AGG, 0.0f);
                acc += log1pf(r * r) * sw[v];
            }
        }
    }

    acc = wsum(acc);
    const int w = threadIdx.x >> 5;
    if ((threadIdx.x & 31) == 0) sred[w] = acc;
    __syncthreads();
    if (threadIdx.x < 8) {
        float v = sred[threadIdx.x];
#pragma unroll
        for (int o = 4; o; o >>= 1) v += __shfl_xor_sync(0xffu, v, o);
        if (threadIdx.x == 0 && v != 0.0f) atomicAdd(&g_agg[b], v);
    }
}

__global__ void pan_final_kernel(float* __restrict__ out, int Npix) {  // grid = B, block = 32
    const int b = blockIdx.x;
    const int l = threadIdx.x;
    __shared__ float4 s_mean[LBL];

    const unsigned long long p = g_pcnt[b][l];
    const float cntk = (float)(unsigned)(p >> 32);
    const float4 m = g_mean[b][l];
    s_mean[l] = m;
    __syncwarp();

    // cnt_k[0] = Npix - sum_{l>0} cnt_k[l]  (label-0 bucket: anything unmasked/non-kernel/label0)
    const float sum_cntk = wsum((l > 0) ? cntk : 0.0f);
    const bool present = (l == 0) ? (sum_cntk < (float)Npix - 0.5f) : (cntk > 0.0f);
    const unsigned pres_mask = __ballot_sync(0xffffffffu, present);
    const int ni = __popc(pres_mask);
    const bool nz = present && (l > 0);
    const unsigned nz_mask = __ballot_sync(0xffffffffu, nz);

    // regularizer
    float sq = m.x * m.x + m.y * m.y + m.z * m.z + m.w * m.w;
    float r = present ? log1pf(sqrtf(sq)) : 0.0f;

    // discrimination: ordered pairs of distinct nz labels
    float dsum = 0.f, dcnt = 0.f;
    if (nz) {
#pragma unroll 1
        for (int j = 1; j < LBL; ++j) {
            if (j != l && ((nz_mask >> j) & 1u)) {
                const float4 mj = s_mean[j];
                float tx = m.x - mj.x, ty = m.y - mj.y;
                float tz = m.z - mj.z, tw = m.w - mj.w;
                float s = tx * tx + ty * ty + tz * tz + tw * tw;
                float rr = fmaxf(2.0f * DELTA_DIS - sqrtf(s), 0.0f);
                dsum += log1pf(rr * rr);
                dcnt += 1.0f;
            }
        }
    }

    r    = wsum(r);
    dsum = wsum(dsum);
    dcnt = wsum(dcnt);

    if (l == 0) {
        float l_agg = g_agg[b] / fmaxf((float)(ni - 1), 1.0f);
        float l_dis = (ni > 2) ? dsum / fmaxf(dcnt, 1.0f) : 0.0f;
        float l_reg = r / fmaxf((float)ni, 1.0f) * REG_W;
        out[b] = (ni <= 1) ? 0.0f : (l_agg + l_dis + l_reg);
    }
}

extern "C" void kernel_launch(void* const* d_in, const int* in_sizes, int n_in,
                              void* d_out, int out_size) {
    const float* emb  = (const float*)d_in[0];
    const int*   inst = (const int*)d_in[1];
    const float* ker  = (const float*)d_in[2];
    const float* tmk  = (const float*)d_in[3];
    float* out = (float*)d_out;

    const int B = out_size;                   // 8
    const int Npix = in_sizes[1] / B;         // 736*736 (divisible by 4)
    const int Nv = Npix / 4;

    pan_zero_kernel<<<1, 256>>>();

    // ~8 float4-iterations per thread
    int bx = (Nv + 256 * 8 - 1) / (256 * 8);
    dim3 grid(bx, B);

    pan_accum_kernel<<<grid, 256>>>((const float4*)emb, (const int4*)inst,
                                    (const float4*)ker, (const float4*)tmk, Nv);
    pan_mean_kernel<<<B, 32>>>();
    pan_agg_kernel<<<grid, 256>>>((const float4*)emb, (const int4*)inst,
                                  (const float4*)tmk, Nv);
    pan_final_kernel<<<B, 32>>>(out, Npix);
}

// round 5
// speedup vs baseline: 4.6547x; 4.6547x over previous
#include <cuda_runtime.h>
#include <math.h>

#define LBL 32
#define MAXB 8
#define SLOTS 128
#define DELTA_AGG 0.5f
#define DELTA_DIS 1.5f
#define REG_W 0.001f

// device-global scratch (no allocations allowed)
// counts packed: lo32 = cnt (mask & label>0), hi32 = cnt_k (mask & kernel & label>0)
__device__ unsigned long long g_cnt_s[MAXB][SLOTS][LBL];
__device__ float4 g_sum_s[MAXB][SLOTS][LBL];
__device__ float4 g_mean[MAXB][LBL];
__device__ float  g_w[MAXB][LBL];      // nz ? 1/max(cnt,1) : 0
__device__ float  g_cntk[MAXB][LBL];
__device__ float  g_agg[MAXB];

__device__ __forceinline__ float wsum(float v) {
#pragma unroll
    for (int o = 16; o; o >>= 1) v += __shfl_xor_sync(0xffffffffu, v, o);
    return v;
}

__device__ __forceinline__ void red_add_v4f32(float4* p, float a, float b, float c, float d) {
    asm volatile("red.global.add.v4.f32 [%0], {%1, %2, %3, %4};"
                 :: "l"(p), "f"(a), "f"(b), "f"(c), "f"(d) : "memory");
}

__global__ void pan_zero_kernel() {   // grid=64, block=256
    const int i = blockIdx.x * blockDim.x + threadIdx.x;
    const int total = MAXB * SLOTS * LBL;           // 32768
    unsigned long long* pc = &g_cnt_s[0][0][0];
    float4* ps = &g_sum_s[0][0][0];
    for (int k = i; k < total; k += gridDim.x * blockDim.x) {
        pc[k] = 0ULL;
        ps[k] = make_float4(0.f, 0.f, 0.f, 0.f);
    }
    if (i < MAXB) g_agg[i] = 0.f;
}

// Pass 1: per-pixel REDs onto slot-spread accumulators. No shared atomics, no flush.
__global__ void pan_accum_kernel(const float4* __restrict__ emb,
                                 const int4* __restrict__ inst,
                                 const float4* __restrict__ ker,
                                 const float4* __restrict__ tmk,
                                 int Nv) {  // Nv = Npix/4
    const int b = blockIdx.y;
    const int slot = blockIdx.x & (SLOTS - 1);
    unsigned long long* cbase = g_cnt_s[b][slot];
    float4* sbase = g_sum_s[b][slot];

    const int4*   ip = inst + (size_t)b * Nv;
    const float4* tm = tmk + (size_t)b * Nv;
    const float4* kn = ker + (size_t)b * Nv;
    const float4* ee = emb + (size_t)b * 4 * Nv;

    for (int i = blockIdx.x * blockDim.x + threadIdx.x; i < Nv;
         i += gridDim.x * blockDim.x) {
        const int4   v4 = ip[i];
        const float4 t4 = tm[i];
        const float4 k4 = kn[i];
        const float4 e0 = ee[i];
        const float4 e1 = ee[i + Nv];
        const float4 e2 = ee[i + 2 * Nv];
        const float4 e3 = ee[i + 3 * Nv];

        const int   vs[4] = {v4.x & 31, v4.y & 31, v4.z & 31, v4.w & 31};
        const float ts[4] = {t4.x, t4.y, t4.z, t4.w};
        const float ks[4] = {k4.x, k4.y, k4.z, k4.w};
        const float a0[4] = {e0.x, e0.y, e0.z, e0.w};
        const float a1[4] = {e1.x, e1.y, e1.z, e1.w};
        const float a2[4] = {e2.x, e2.y, e2.z, e2.w};
        const float a3[4] = {e3.x, e3.y, e3.z, e3.w};

#pragma unroll
        for (int j = 0; j < 4; ++j) {
            const bool t  = ts[j] > 0.5f;
            const int  v  = vs[j];
            const bool li = t && (v > 0);
            const bool kk = li && (ks[j] > 0.5f);
            if (li)
                atomicAdd(&cbase[v], 1ULL + (kk ? (1ULL << 32) : 0ULL));
            if (kk)
                red_add_v4f32(&sbase[v], a0[j], a1[j], a2[j], a3[j]);
        }
    }
}

// Collapse slots -> mean, weight, cnt_k per (batch, label).
__global__ void pan_reduce_kernel() {   // grid = (LBL, MAXB), block = SLOTS
    const int l = blockIdx.x;
    const int b = blockIdx.y;
    const int s = threadIdx.x;
    const int w = s >> 5;
    __shared__ float sred[SLOTS / 32][6];

    const unsigned long long c = g_cnt_s[b][s][l];
    const float4 v = g_sum_s[b][s][l];
    float t0 = (float)(unsigned)(c & 0xffffffffu);   // cnt
    float t1 = (float)(unsigned)(c >> 32);           // cnt_k
    float t2 = v.x, t3 = v.y, t4 = v.z, t5 = v.w;

    t0 = wsum(t0); t1 = wsum(t1); t2 = wsum(t2);
    t3 = wsum(t3); t4 = wsum(t4); t5 = wsum(t5);
    if ((s & 31) == 0) {
        sred[w][0] = t0; sred[w][1] = t1; sred[w][2] = t2;
        sred[w][3] = t3; sred[w][4] = t4; sred[w][5] = t5;
    }
    __syncthreads();
    if (s == 0) {
        float r[6];
#pragma unroll
        for (int k = 0; k < 6; ++k) {
            float acc = 0.f;
#pragma unroll
            for (int ww = 0; ww < SLOTS / 32; ++ww) acc += sred[ww][k];
            r[k] = acc;
        }
        const float cnt = r[0], ck = r[1];
        const float ic = (l > 0) ? 1.0f / fmaxf(ck, 1.0f) : 0.0f;  // row 0 forced to 0
        g_mean[b][l] = make_float4(r[2] * ic, r[3] * ic, r[4] * ic, r[5] * ic);
        g_w[b][l] = (l > 0 && ck > 0.0f) ? 1.0f / fmaxf(cnt, 1.0f) : 0.0f;
        g_cntk[b][l] = ck;
    }
}

// Pass 2: per-pixel aggregation value with precomputed per-label weight -> scalar sum.
__global__ void pan_agg_kernel(const float4* __restrict__ emb,
                               const int4* __restrict__ inst,
                               const float4* __restrict__ tmk,
                               int Nv) {
    const int b = blockIdx.y;
    __shared__ float4 sm[LBL];
    __shared__ float  sw[LBL];
    __shared__ float  sred[8];
    if (threadIdx.x < LBL) {
        sm[threadIdx.x] = g_mean[b][threadIdx.x];
        sw[threadIdx.x] = g_w[b][threadIdx.x];
    }
    __syncthreads();

    const int4*   ip = inst + (size_t)b * Nv;
    const float4* tm = tmk + (size_t)b * Nv;
    const float4* ee = emb + (size_t)b * 4 * Nv;

    float acc = 0.0f;
    for (int i = blockIdx.x * blockDim.x + threadIdx.x; i < Nv;
         i += gridDim.x * blockDim.x) {
        const int4   v4 = ip[i];
        const float4 t4 = tm[i];
        const float4 e0 = ee[i];
        const float4 e1 = ee[i + Nv];
        const float4 e2 = ee[i + 2 * Nv];
        const float4 e3 = ee[i + 3 * Nv];

        const int   vs[4] = {v4.x & 31, v4.y & 31, v4.z & 31, v4.w & 31};
        const float ts[4] = {t4.x, t4.y, t4.z, t4.w};
        const float a0[4] = {e0.x, e0.y, e0.z, e0.w};
        const float a1[4] = {e1.x, e1.y, e1.z, e1.w};
        const float a2[4] = {e2.x, e2.y, e2.z, e2.w};
        const float a3[4] = {e3.x, e3.y, e3.z, e3.w};

#pragma unroll
        for (int j = 0; j < 4; ++j) {
            const bool t = ts[j] > 0.5f;
            const int  v = vs[j];
            if (t && v > 0) {
                const float4 m = sm[v];
                float dx = a0[j] - m.x;
                float dy = a1[j] - m.y;
                float dz = a2[j] - m.z;
                float dw = a3[j] - m.w;
                float sq = dx * dx + dy * dy + dz * dz + dw * dw;
                float r  = fmaxf(sqrtf(sq) - DELTA_AGG, 0.0f);
                acc += log1pf(r * r) * sw[v];
            }
        }
    }

    acc = wsum(acc);
    const int w = threadIdx.x >> 5;
    if ((threadIdx.x & 31) == 0) sred[w] = acc;
    __syncthreads();
    if (threadIdx.x < 8) {
        float v = sred[threadIdx.x];
#pragma unroll
        for (int o = 4; o; o >>= 1) v += __shfl_xor_sync(0xffu, v, o);
        if (threadIdx.x == 0 && v != 0.0f) atomicAdd(&g_agg[b], v);
    }
}

__global__ void pan_final_kernel(float* __restrict__ out, int Npix) {  // grid = B, block = 32
    const int b = blockIdx.x;
    const int l = threadIdx.x;
    __shared__ float4 s_mean[LBL];

    const float cntk = g_cntk[b][l];
    const float4 m = g_mean[b][l];
    s_mean[l] = m;
    __syncwarp();

    // cnt_k[0] = Npix - sum_{l>0} cnt_k[l]  (label-0 bucket: unmasked/non-kernel/label0)
    const float sum_cntk = wsum((l > 0) ? cntk : 0.0f);
    const bool present = (l == 0) ? (sum_cntk < (float)Npix - 0.5f) : (cntk > 0.0f);
    const unsigned pres_mask = __ballot_sync(0xffffffffu, present);
    const int ni = __popc(pres_mask);
    const bool nz = present && (l > 0);
    const unsigned nz_mask = __ballot_sync(0xffffffffu, nz);

    // regularizer
    float sq = m.x * m.x + m.y * m.y + m.z * m.z + m.w * m.w;
    float r = present ? log1pf(sqrtf(sq)) : 0.0f;

    // discrimination: ordered pairs of distinct nz labels
    float dsum = 0.f, dcnt = 0.f;
    if (nz) {
#pragma unroll 1
        for (int j = 1; j < LBL; ++j) {
            if (j != l && ((nz_mask >> j) & 1u)) {
                const float4 mj = s_mean[j];
                float tx = m.x - mj.x, ty = m.y - mj.y;
                float tz = m.z - mj.z, tw = m.w - mj.w;
                float s = tx * tx + ty * ty + tz * tz + tw * tw;
                float rr = fmaxf(2.0f * DELTA_DIS - sqrtf(s), 0.0f);
                dsum += log1pf(rr * rr);
                dcnt += 1.0f;
            }
        }
    }

    r    = wsum(r);
    dsum = wsum(dsum);
    dcnt = wsum(dcnt);

    if (l == 0) {
        float l_agg = g_agg[b] / fmaxf((float)(ni - 1), 1.0f);
        float l_dis = (ni > 2) ? dsum / fmaxf(dcnt, 1.0f) : 0.0f;
        float l_reg = r / fmaxf((float)ni, 1.0f) * REG_W;
        out[b] = (ni <= 1) ? 0.0f : (l_agg + l_dis + l_reg);
    }
}

extern "C" void kernel_launch(void* const* d_in, const int* in_sizes, int n_in,
                              void* d_out, int out_size) {
    const float* emb  = (const float*)d_in[0];
    const int*   inst = (const int*)d_in[1];
    const float* ker  = (const float*)d_in[2];
    const float* tmk  = (const float*)d_in[3];
    float* out = (float*)d_out;

    const int B = out_size;                   // 8
    const int Npix = in_sizes[1] / B;         // 736*736 (divisible by 4)
    const int Nv = Npix / 4;

    pan_zero_kernel<<<64, 256>>>();

    // ~2 float4-iterations per thread -> ~2120 blocks for occupancy
    int bx = (Nv + 256 * 2 - 1) / (256 * 2);
    dim3 grid(bx, B);

    pan_accum_kernel<<<grid, 256>>>((const float4*)emb, (const int4*)inst,
                                    (const float4*)ker, (const float4*)tmk, Nv);
    pan_reduce_kernel<<<dim3(LBL, B), SLOTS>>>();
    pan_agg_kernel<<<grid, 256>>>((const float4*)emb, (const int4*)inst,
                                  (const float4*)tmk, Nv);
    pan_final_kernel<<<B, 32>>>(out, Npix);
}

// round 7
// speedup vs baseline: 5.0433x; 1.0835x over previous
#include <cuda_runtime.h>
#include <math.h>

#define LBL 32
#define MAXB 8
#define SLOTS 128
#define MAXNV 135424          // 736*736/4 float4-groups per batch
#define DELTA_AGG 0.5f
#define DELTA_DIS 1.5f
#define REG_W 0.001f

// device-global scratch (zero-initialized at module load; every run restores zeros)
__device__ unsigned long long g_cnt_s[MAXB][SLOTS][LBL]; // lo32=cnt(mask,v>0) hi32=cnt_k
__device__ float4   g_sum_s[MAXB][SLOTS][LBL];
__device__ float4   g_mean[MAXB][LBL];
__device__ float    g_w[MAXB][LBL];          // nz ? 1/max(cnt,1) : 0  (w[0]=0)
__device__ float    g_cntk[MAXB][LBL];
__device__ float    g_agg[MAXB];
__device__ unsigned g_packed[MAXB][MAXNV];   // 4 packed labels per u32
__device__ int      g_done;

__device__ __forceinline__ float wsum(float v) {
#pragma unroll
    for (int o = 16; o; o >>= 1) v += __shfl_xor_sync(0xffffffffu, v, o);
    return v;
}

__device__ __forceinline__ void red_add_v4f32(float4* p, float a, float b, float c, float d) {
    asm volatile("red.global.add.v4.f32 [%0], {%1, %2, %3, %4};"
                 :: "l"(p), "f"(a), "f"(b), "f"(c), "f"(d) : "memory");
}

// ---------------------------------------------------------------------------
// Pass 1: slot-spread REDs for counts/sums + packed label store.
// inst/ker/tmk are last-use here (streamed); emb stays L2-resident for pass 2.
// ---------------------------------------------------------------------------
__global__ void __launch_bounds__(256, 6)
pan_accum_kernel(const float4* __restrict__ emb,
                 const int4* __restrict__ inst,
                 const float4* __restrict__ ker,
                 const float4* __restrict__ tmk,
                 int Nv) {
    const int b = blockIdx.y;
    const int slot = blockIdx.x & (SLOTS - 1);
    unsigned long long* cbase = g_cnt_s[b][slot];
    float4* sbase = g_sum_s[b][slot];
    unsigned* pk = g_packed[b];

    const int4*   ip = inst + (size_t)b * Nv;
    const float4* tm = tmk + (size_t)b * Nv;
    const float4* kn = ker + (size_t)b * Nv;
    const float4* ee = emb + (size_t)b * 4 * Nv;

    for (int i = blockIdx.x * blockDim.x + threadIdx.x; i < Nv;
         i += gridDim.x * blockDim.x) {
        const int4   v4 = __ldcs(ip + i);
        const float4 t4 = __ldcs(tm + i);
        const float4 k4 = __ldcs(kn + i);
        const float4 e0 = ee[i];
        const float4 e1 = ee[i + Nv];
        const float4 e2 = ee[i + 2 * Nv];
        const float4 e3 = ee[i + 3 * Nv];

        const int   vs[4] = {v4.x & 31, v4.y & 31, v4.z & 31, v4.w & 31};
        const float ts[4] = {t4.x, t4.y, t4.z, t4.w};
        const float ks[4] = {k4.x, k4.y, k4.z, k4.w};
        const float a0[4] = {e0.x, e0.y, e0.z, e0.w};
        const float a1[4] = {e1.x, e1.y, e1.z, e1.w};
        const float a2[4] = {e2.x, e2.y, e2.z, e2.w};
        const float a3[4] = {e3.x, e3.y, e3.z, e3.w};

        unsigned lp = 0;
#pragma unroll
        for (int j = 0; j < 4; ++j) {
            const bool t  = ts[j] > 0.5f;
            const int  v  = vs[j];
            const bool li = t && (v > 0);
            const bool kk = li && (ks[j] > 0.5f);
            if (li) {
                lp |= (unsigned)v << (8 * j);
                atomicAdd(&cbase[v], 1ULL + (kk ? (1ULL << 32) : 0ULL));
            }
            if (kk)
                red_add_v4f32(&sbase[v], a0[j], a1[j], a2[j], a3[j]);
        }
        pk[i] = lp;
    }
}

// ---------------------------------------------------------------------------
// Collapse slots -> mean / weight / cnt_k, restoring scratch to zero.
// ---------------------------------------------------------------------------
__global__ void pan_reduce_kernel() {   // grid = (LBL, MAXB), block = SLOTS
    const int l = blockIdx.x;
    const int b = blockIdx.y;
    const int s = threadIdx.x;
    const int w = s >> 5;
    __shared__ float sred[SLOTS / 32][6];

    const unsigned long long c = g_cnt_s[b][s][l];
    const float4 v = g_sum_s[b][s][l];
    g_cnt_s[b][s][l] = 0ULL;                           // restore zero-state
    g_sum_s[b][s][l] = make_float4(0.f, 0.f, 0.f, 0.f);

    float t0 = (float)(unsigned)(c & 0xffffffffu);     // cnt
    float t1 = (float)(unsigned)(c >> 32);             // cnt_k
    float t2 = v.x, t3 = v.y, t4 = v.z, t5 = v.w;

    t0 = wsum(t0); t1 = wsum(t1); t2 = wsum(t2);
    t3 = wsum(t3); t4 = wsum(t4); t5 = wsum(t5);
    if ((s & 31) == 0) {
        sred[w][0] = t0; sred[w][1] = t1; sred[w][2] = t2;
        sred[w][3] = t3; sred[w][4] = t4; sred[w][5] = t5;
    }
    __syncthreads();
    if (s == 0) {
        float r[6];
#pragma unroll
        for (int k = 0; k < 6; ++k) {
            float acc = 0.f;
#pragma unroll
            for (int ww = 0; ww < SLOTS / 32; ++ww) acc += sred[ww][k];
            r[k] = acc;
        }
        const float cnt = r[0], ck = r[1];
        const float ic = (l > 0) ? 1.0f / fmaxf(ck, 1.0f) : 0.0f;  // row 0 forced to 0
        g_mean[b][l] = make_float4(r[2] * ic, r[3] * ic, r[4] * ic, r[5] * ic);
        g_w[b][l] = (l > 0 && ck > 0.0f) ? 1.0f / fmaxf(cnt, 1.0f) : 0.0f;
        g_cntk[b][l] = ck;
    }
}

// ---------------------------------------------------------------------------
// Pass 2: branchless per-pixel aggregation (emb + packed labels only),
// fused finalization in the last block (atomic-counter pattern).
// ---------------------------------------------------------------------------
__global__ void __launch_bounds__(256, 8)
pan_agg_kernel(const float4* __restrict__ emb,
               float* __restrict__ out,
               int Nv, int Npix, int nBlocks) {
    const int b = blockIdx.y;
    __shared__ float4 sm[LBL];
    __shared__ float  sw[LBL];
    __shared__ float  sred[8];
    __shared__ int    is_last;
    if (threadIdx.x < LBL) {
        sm[threadIdx.x] = g_mean[b][threadIdx.x];
        sw[threadIdx.x] = g_w[b][threadIdx.x];
    }
    __syncthreads();

    const unsigned* pk = g_packed[b];
    const float4*   ee = emb + (size_t)b * 4 * Nv;

    float acc = 0.0f;
    for (int i = blockIdx.x * blockDim.x + threadIdx.x; i < Nv;
         i += gridDim.x * blockDim.x) {
        const unsigned lp = __ldcs(pk + i);
        const float4 e0 = __ldcs(ee + i);
        const float4 e1 = __ldcs(ee + i + Nv);
        const float4 e2 = __ldcs(ee + i + 2 * Nv);
        const float4 e3 = __ldcs(ee + i + 3 * Nv);

        const float a0[4] = {e0.x, e0.y, e0.z, e0.w};
        const float a1[4] = {e1.x, e1.y, e1.z, e1.w};
        const float a2[4] = {e2.x, e2.y, e2.z, e2.w};
        const float a3[4] = {e3.x, e3.y, e3.z, e3.w};

#pragma unroll
        for (int j = 0; j < 4; ++j) {
            const int v = (lp >> (8 * j)) & 0xff;    // 0 when masked-out -> weight 0
            const float4 m = sm[v];
            float dx = a0[j] - m.x;
            float dy = a1[j] - m.y;
            float dz = a2[j] - m.z;
            float dw = a3[j] - m.w;
            float sq = dx * dx + dy * dy + dz * dz + dw * dw;
            float r  = fmaxf(sqrtf(sq) - DELTA_AGG, 0.0f);
            acc += log1pf(r * r) * sw[v];
        }
    }

    acc = wsum(acc);
    const int w = threadIdx.x >> 5;
    if ((threadIdx.x & 31) == 0) sred[w] = acc;
    __syncthreads();
    if (threadIdx.x < 8) {
        float v = sred[threadIdx.x];
#pragma unroll
        for (int o = 4; o; o >>= 1) v += __shfl_xor_sync(0xffu, v, o);
        if (threadIdx.x == 0) {
            if (v != 0.0f) atomicAdd(&g_agg[b], v);
            __threadfence();
            int old = atomicAdd(&g_done, 1);
            is_last = (old == nBlocks - 1) ? 1 : 0;
        }
    }
    __syncthreads();

    if (is_last) {
        // 8 warps: warp wb finalizes batch wb, lane l = label l
        __shared__ float4 s_mean[MAXB][LBL];
        const int wb = threadIdx.x >> 5;
        const int l  = threadIdx.x & 31;

        const float cntk = g_cntk[wb][l];
        const float4 m = g_mean[wb][l];
        s_mean[wb][l] = m;
        __syncwarp();

        // cnt_k[0] = Npix - sum_{l>0} cnt_k[l]
        const float sum_cntk = wsum((l > 0) ? cntk : 0.0f);
        const bool present = (l == 0) ? (sum_cntk < (float)Npix - 0.5f) : (cntk > 0.0f);
        const unsigned pres_mask = __ballot_sync(0xffffffffu, present);
        const int ni = __popc(pres_mask);
        const bool nz = present && (l > 0);
        const unsigned nz_mask = __ballot_sync(0xffffffffu, nz);

        float sq = m.x * m.x + m.y * m.y + m.z * m.z + m.w * m.w;
        float r = present ? log1pf(sqrtf(sq)) : 0.0f;

        float dsum = 0.f, dcnt = 0.f;
        if (nz) {
#pragma unroll 1
            for (int j = 1; j < LBL; ++j) {
                if (j != l && ((nz_mask >> j) & 1u)) {
                    const float4 mj = s_mean[wb][j];
                    float tx = m.x - mj.x, ty = m.y - mj.y;
                    float tz = m.z - mj.z, tw = m.w - mj.w;
                    float s = tx * tx + ty * ty + tz * tz + tw * tw;
                    float rr = fmaxf(2.0f * DELTA_DIS - sqrtf(s), 0.0f);
                    dsum += log1pf(rr * rr);
                    dcnt += 1.0f;
                }
            }
        }

        r    = wsum(r);
        dsum = wsum(dsum);
        dcnt = wsum(dcnt);

        if (l == 0) {
            float la = atomicAdd(&g_agg[wb], 0.0f);       // read through L2
            float l_agg = la / fmaxf((float)(ni - 1), 1.0f);
            float l_dis = (ni > 2) ? dsum / fmaxf(dcnt, 1.0f) : 0.0f;
            float l_reg = r / fmaxf((float)ni, 1.0f) * REG_W;
            out[wb] = (ni <= 1) ? 0.0f : (l_agg + l_dis + l_reg);
            g_agg[wb] = 0.0f;                             // restore zero-state
        }
        if (threadIdx.x == 0) g_done = 0;
    }
}

extern "C" void kernel_launch(void* const* d_in, const int* in_sizes, int n_in,
                              void* d_out, int out_size) {
    const float* emb  = (const float*)d_in[0];
    const int*   inst = (const int*)d_in[1];
    const float* ker  = (const float*)d_in[2];
    const float* tmk  = (const float*)d_in[3];
    float* out = (float*)d_out;

    const int B = out_size;                   // 8
    const int Npix = in_sizes[1] / B;         // 736*736
    const int Nv = Npix / 4;                  // fits MAXNV

    int bx = (Nv + 256 * 2 - 1) / (256 * 2);  // ~2 float4-iters per thread
    dim3 grid(bx, B);

    pan_accum_kernel<<<grid, 256>>>((const float4*)emb, (const int4*)inst,
                                    (const float4*)ker, (const float4*)tmk, Nv);
    pan_reduce_kernel<<<dim3(LBL, B), SLOTS>>>();
    pan_agg_kernel<<<grid, 256>>>((const float4*)emb, out, Nv, Npix, bx * B);
}